// round 2
// baseline (speedup 1.0000x reference)
#include <cuda_runtime.h>
#include <cstdint>

#define NB   4
#define DIM  64
#define NSEQ 4096
#define NCLS 19

// ---------------- scratch (no allocations allowed) ----------------
__device__ float g_q    [NB * NSEQ * DIM];   // 4 MB
__device__ float g_v    [NB * NSEQ * DIM];   // 4 MB
__device__ float g_attnT[NB * DIM * NSEQ];   // 4 MB, [b][dim][n] transposed
__device__ float g_x1   [NB * NSEQ * DIM];   // 4 MB, natural [B,H,W,C]

// ---------------- helpers ----------------
static __device__ __forceinline__ float tfround(float x) {
    uint32_t r;
    asm("cvt.rna.tf32.f32 %0, %1;" : "=r"(r) : "f"(x));
    return __uint_as_float(r);
}

static __device__ __forceinline__ void mma8(float* d, const uint32_t* a, const uint32_t* b) {
    asm volatile(
        "mma.sync.aligned.m16n8k8.row.col.f32.tf32.tf32.f32 "
        "{%0,%1,%2,%3}, {%4,%5,%6,%7}, {%8,%9}, {%0,%1,%2,%3};\n"
        : "+f"(d[0]), "+f"(d[1]), "+f"(d[2]), "+f"(d[3])
        : "r"(a[0]), "r"(a[1]), "r"(a[2]), "r"(a[3]), "r"(b[0]), "r"(b[1]));
}

static __device__ __forceinline__ float sigm(float x) {
    return 1.0f / (1.0f + __expf(-x));
}

static __device__ __forceinline__ void cp16(uint32_t dst_smem, const void* src) {
    asm volatile("cp.async.ca.shared.global [%0], [%1], 16;\n" :: "r"(dst_smem), "l"(src));
}

// ---------------- K1/K3: gather + q,v projection ----------------
// mode 0 (height): xs[c][h] = feature[b,h,s(=w),c]
// mode 1 (width):  xs[c][w] = feature[b,s(=h),w,c] + h_gate*attnT_h[b][s][w*64+c]; also writes g_x1
// Output rows n = s*64 + c, q/v stored [B][NSEQ][DIM] tf32-rounded.
#define QV_SMEM ((64 * 65 + 2 * 64 * 64) * 4)

__global__ __launch_bounds__(256) void qv_kernel(
    const float* __restrict__ feature,
    const float* __restrict__ gate,          // used only in mode 1
    const float* __restrict__ Wq, const float* __restrict__ bq,
    const float* __restrict__ Wv, const float* __restrict__ bv,
    int mode)
{
    extern __shared__ float sm[];
    float* xs  = sm;                 // 64 x 65 (padded)
    float* wqs = sm + 64 * 65;       // 64 x 64
    float* wvs = wqs + 64 * 64;      // 64 x 64

    const int b   = blockIdx.y;
    const int s   = blockIdx.x;
    const int tid = threadIdx.x;

    // load weights (row-major [k][j], contiguous, conflict-free)
    #pragma unroll
    for (int i = 0; i < 16; i++) {
        int lin = tid + 256 * i;
        wqs[lin] = Wq[lin];
        wvs[lin] = Wv[lin];
    }

    // gather x tile
    if (mode == 0) {
        size_t fb = (size_t)b * 262144 + (size_t)s * 64;
        #pragma unroll
        for (int i = 0; i < 16; i++) {
            int lin = tid + 256 * i;            // lin = h*64 + c
            float val = feature[fb + (size_t)(lin >> 6) * 4096 + (lin & 63)];
            xs[(lin & 63) * 65 + (lin >> 6)] = val;
        }
    } else {
        float gt = gate[0];
        size_t fb = (size_t)b * 262144 + (size_t)s * 4096;
        const float* at = g_attnT + (size_t)(b * 64 + s) * 4096;
        #pragma unroll
        for (int i = 0; i < 16; i++) {
            int lin = tid + 256 * i;            // lin = w*64 + c
            float val = feature[fb + lin] + gt * at[lin];
            g_x1[fb + lin] = val;
            xs[(lin & 63) * 65 + (lin >> 6)] = val;
        }
    }
    __syncthreads();

    const int tx = tid & 15;   // output cols tx*4..+3
    const int ty = tid >> 4;   // output rows ty*4..+3

    float accq[4][4], accv[4][4];
    #pragma unroll
    for (int i = 0; i < 4; i++)
        #pragma unroll
        for (int j = 0; j < 4; j++) { accq[i][j] = 0.f; accv[i][j] = 0.f; }

    #pragma unroll 8
    for (int k = 0; k < 64; k++) {
        float4 wq4 = *(const float4*)(wqs + k * 64 + tx * 4);
        float4 wv4 = *(const float4*)(wvs + k * 64 + tx * 4);
        #pragma unroll
        for (int i = 0; i < 4; i++) {
            float x = xs[(ty * 4 + i) * 65 + k];
            accq[i][0] += x * wq4.x; accq[i][1] += x * wq4.y;
            accq[i][2] += x * wq4.z; accq[i][3] += x * wq4.w;
            accv[i][0] += x * wv4.x; accv[i][1] += x * wv4.y;
            accv[i][2] += x * wv4.z; accv[i][3] += x * wv4.w;
        }
    }

    float4 bq4 = *(const float4*)(bq + tx * 4);
    float4 bv4 = *(const float4*)(bv + tx * 4);
    size_t ob = ((size_t)b * NSEQ + (size_t)s * 64) * 64;
    #pragma unroll
    for (int i = 0; i < 4; i++) {
        int r = ty * 4 + i;
        float4 oq, ov;
        oq.x = tfround(accq[i][0] + bq4.x);
        oq.y = tfround(accq[i][1] + bq4.y);
        oq.z = tfround(accq[i][2] + bq4.z);
        oq.w = tfround(accq[i][3] + bq4.w);
        ov.x = tfround(accv[i][0] + bv4.x);
        ov.y = tfround(accv[i][1] + bv4.y);
        ov.z = tfround(accv[i][2] + bv4.z);
        ov.w = tfround(accv[i][3] + bv4.w);
        *(float4*)(g_q + ob + (size_t)r * 64 + tx * 4) = oq;
        *(float4*)(g_v + ob + (size_t)r * 64 + tx * 4) = ov;
    }
}

// ---------------- K2/K4: fused sigmoid attention ----------------
// out[n][d] = sum_m sigmoid(q[n].q[m]/8) * v[m][d]; writes g_attnT[b][d][n].
// BM=128 rows per block, BN=64 m-columns per iteration, tf32 mma, fp32 accum.
// K/V tiles double-buffered via cp.async so tile m+1 streams in during compute of m.
#define KV_STRIDE (64 * 68)
#define ATTN_SMEM ((4 * KV_STRIDE + 128 * 68) * 4)

__global__ __launch_bounds__(256, 1) void attn_kernel()
{
    extern __shared__ float sm[];
    // ksh buf0, vsh buf0, ksh buf1, vsh buf1, ssh
    float* kv  = sm;                       // 4 x (64 x 68)
    float* ssh = sm + 4 * KV_STRIDE;       // 128 x 68 (Q-stage / S / O-transpose)

    const int b   = blockIdx.y;
    const int n0  = blockIdx.x * 128;
    const int tid  = threadIdx.x;
    const int lane = tid & 31;
    const int wp   = tid >> 5;
    const int g    = lane >> 2;
    const int t    = lane & 3;
    const int row0 = wp * 16 + g;

    const float* qb = g_q + (size_t)b * NSEQ * DIM;
    const float* vb = g_v + (size_t)b * NSEQ * DIM;

    // per-thread staging coordinates (4 float4 per tile per thread, for K and V each)
    const int sr = tid >> 4;           // rows sr, sr+16, sr+32, sr+48
    const int sc4 = (tid & 15) * 4;    // column group

    // prefetch tile 0 into buffer 0 (overlaps with Q-fragment preload below)
    {
        uint32_t kdst = (uint32_t)__cvta_generic_to_shared(kv + sr * 68 + sc4);
        uint32_t vdst = kdst + (uint32_t)(KV_STRIDE * 4);
        #pragma unroll
        for (int i = 0; i < 4; i++) {
            int r = sr + 16 * i;
            cp16(kdst + i * (16 * 68 * 4), qb + (size_t)r * 64 + sc4);
            cp16(vdst + i * (16 * 68 * 4), vb + (size_t)r * 64 + sc4);
        }
        asm volatile("cp.async.commit_group;\n");
    }

    // stage Q block, preload A fragments for all 8 k-steps (register-resident)
    #pragma unroll
    for (int i = 0; i < 8; i++) {
        int idx = tid + 256 * i;
        int r = idx >> 4, c4 = (idx & 15) * 4;
        *(float4*)(ssh + r * 68 + c4) = *(const float4*)(qb + (size_t)(n0 + r) * 64 + c4);
    }
    __syncthreads();
    uint32_t qa[8][4];
    #pragma unroll
    for (int kk = 0; kk < 8; kk++) {
        qa[kk][0] = __float_as_uint(ssh[ row0      * 68 + kk * 8 + t]);
        qa[kk][1] = __float_as_uint(ssh[(row0 + 8) * 68 + kk * 8 + t]);
        qa[kk][2] = __float_as_uint(ssh[ row0      * 68 + kk * 8 + t + 4]);
        qa[kk][3] = __float_as_uint(ssh[(row0 + 8) * 68 + kk * 8 + t + 4]);
    }

    float oacc[8][4];
    #pragma unroll
    for (int j = 0; j < 8; j++)
        #pragma unroll
        for (int e = 0; e < 4; e++) oacc[j][e] = 0.f;

    for (int it = 0; it < 64; it++) {
        const int   cur = it & 1;
        const float* ksh = kv + (2 * cur)     * KV_STRIDE;
        const float* vsh = kv + (2 * cur + 1) * KV_STRIDE;

        // prefetch next tile into the other buffer
        if (it < 63) {
            int mn = (it + 1) * 64;
            uint32_t kdst = (uint32_t)__cvta_generic_to_shared(
                kv + (2 * (cur ^ 1)) * KV_STRIDE + sr * 68 + sc4);
            uint32_t vdst = kdst + (uint32_t)(KV_STRIDE * 4);
            #pragma unroll
            for (int i = 0; i < 4; i++) {
                int r = mn + sr + 16 * i;
                cp16(kdst + i * (16 * 68 * 4), qb + (size_t)r * 64 + sc4);
                cp16(vdst + i * (16 * 68 * 4), vb + (size_t)r * 64 + sc4);
            }
            asm volatile("cp.async.commit_group;\n");
            asm volatile("cp.async.wait_group 1;\n");
        } else {
            asm volatile("cp.async.wait_group 0;\n");
        }
        __syncthreads();   // cur buffer fully staged + ssh (Q stage / prev S) free

        // GEMM1: S = Q @ K^T  (16x64 per warp)
        float sacc[8][4];
        #pragma unroll
        for (int j = 0; j < 8; j++)
            #pragma unroll
            for (int e = 0; e < 4; e++) sacc[j][e] = 0.f;

        #pragma unroll
        for (int kk = 0; kk < 8; kk++) {
            #pragma unroll
            for (int j = 0; j < 8; j++) {
                uint32_t bb[2];
                bb[0] = __float_as_uint(ksh[(j * 8 + g) * 68 + kk * 8 + t]);
                bb[1] = __float_as_uint(ksh[(j * 8 + g) * 68 + kk * 8 + t + 4]);
                mma8(sacc[j], qa[kk], bb);
            }
        }

        // sigmoid + tf32 round, deposit S into warp-private smem slice
        #pragma unroll
        for (int j = 0; j < 8; j++) {
            float s0 = sigm(sacc[j][0] * 0.125f);
            float s1 = sigm(sacc[j][1] * 0.125f);
            float s2 = sigm(sacc[j][2] * 0.125f);
            float s3 = sigm(sacc[j][3] * 0.125f);
            ssh[ row0      * 68 + j * 8 + 2 * t]     = tfround(s0);
            ssh[ row0      * 68 + j * 8 + 2 * t + 1] = tfround(s1);
            ssh[(row0 + 8) * 68 + j * 8 + 2 * t]     = tfround(s2);
            ssh[(row0 + 8) * 68 + j * 8 + 2 * t + 1] = tfround(s3);
        }
        __syncwarp();

        // GEMM2: O += S @ V
        #pragma unroll
        for (int kk = 0; kk < 8; kk++) {
            uint32_t aa[4];
            aa[0] = __float_as_uint(ssh[ row0      * 68 + kk * 8 + t]);
            aa[1] = __float_as_uint(ssh[(row0 + 8) * 68 + kk * 8 + t]);
            aa[2] = __float_as_uint(ssh[ row0      * 68 + kk * 8 + t + 4]);
            aa[3] = __float_as_uint(ssh[(row0 + 8) * 68 + kk * 8 + t + 4]);
            #pragma unroll
            for (int j = 0; j < 8; j++) {
                uint32_t bb[2];
                bb[0] = __float_as_uint(vsh[(kk * 8 + t)     * 68 + j * 8 + g]);
                bb[1] = __float_as_uint(vsh[(kk * 8 + t + 4) * 68 + j * 8 + g]);
                mma8(oacc[j], aa, bb);
            }
        }
        __syncthreads();   // compute on cur buf done before next iter's prefetch reuses it
    }

    // epilogue: smem transpose -> coalesced write of attnT[b][d][n0+r]
    #pragma unroll
    for (int j = 0; j < 8; j++) {
        ssh[ row0      * 68 + j * 8 + 2 * t]     = oacc[j][0];
        ssh[ row0      * 68 + j * 8 + 2 * t + 1] = oacc[j][1];
        ssh[(row0 + 8) * 68 + j * 8 + 2 * t]     = oacc[j][2];
        ssh[(row0 + 8) * 68 + j * 8 + 2 * t + 1] = oacc[j][3];
    }
    __syncthreads();
    float* ab = g_attnT + (size_t)b * DIM * NSEQ;
    #pragma unroll
    for (int i = 0; i < 32; i++) {
        int idx = tid + 256 * i;        // 64*128 elems
        int d = idx >> 7, r = idx & 127;
        ab[(size_t)d * NSEQ + n0 + r] = ssh[r * 68 + d];
    }
}

// ---------------- K5: final gate ----------------
__global__ __launch_bounds__(256) void final_kernel(
    const float* __restrict__ feature,
    const float* __restrict__ predict,
    const float* __restrict__ wgate,
    const float* __restrict__ convw,
    const float* __restrict__ convb,
    float* __restrict__ out)
{
    __shared__ float psh[64];
    __shared__ float cw[NCLS];

    const int b = blockIdx.y;
    const int h = blockIdx.x;
    const int tid = threadIdx.x;

    if (tid < NCLS) cw[tid] = convw[tid];
    __syncthreads();

    if (tid < 64) {
        int w = tid;
        const float* pp = predict + ((size_t)(b * 64 + h) * 64 + w) * NCLS;
        float acc = convb[0];
        #pragma unroll
        for (int nc = 0; nc < NCLS; nc++) {
            float x = pp[nc];
            acc += cw[nc] / (1.0f + __expf(x));    // (1 - sigmoid(x)) = sigmoid(-x)
        }
        psh[w] = acc;
    }
    __syncthreads();

    float wg = wgate[0];
    size_t base = (size_t)(b * 64 + h) * 4096;
    #pragma unroll
    for (int i = 0; i < 16; i++) {
        int lin = tid + 256 * i;     // lin = w*64 + c
        int w = lin >> 6, c = lin & 63;
        float feat = feature[base + lin] + g_x1[base + lin]
                   + wg * g_attnT[(size_t)(b * 64 + w) * 4096 + h * 64 + c];
        out[base + lin] = psh[w] * feat;
    }
}

// ---------------- launch ----------------
extern "C" void kernel_launch(void* const* d_in, const int* in_sizes, int n_in,
                              void* d_out, int out_size)
{
    (void)in_sizes; (void)n_in; (void)out_size;
    const float* feature = (const float*)d_in[0];
    const float* predict = (const float*)d_in[1];
    const float* hq_w    = (const float*)d_in[2];
    const float* hq_b    = (const float*)d_in[3];
    const float* hv_w    = (const float*)d_in[4];
    const float* hv_b    = (const float*)d_in[5];
    const float* wq_w    = (const float*)d_in[6];
    const float* wq_b    = (const float*)d_in[7];
    const float* wv_w    = (const float*)d_in[8];
    const float* wv_b    = (const float*)d_in[9];
    const float* h_gate  = (const float*)d_in[10];
    const float* w_gate  = (const float*)d_in[11];
    const float* conv_w  = (const float*)d_in[12];
    const float* conv_b  = (const float*)d_in[13];
    float* out = (float*)d_out;

    cudaFuncSetAttribute(qv_kernel,   cudaFuncAttributeMaxDynamicSharedMemorySize, QV_SMEM);
    cudaFuncSetAttribute(attn_kernel, cudaFuncAttributeMaxDynamicSharedMemorySize, ATTN_SMEM);

    dim3 gqv(64, NB);
    dim3 gat(32, NB);

    // height pass
    qv_kernel<<<gqv, 256, QV_SMEM>>>(feature, nullptr, hq_w, hq_b, hv_w, hv_b, 0);
    attn_kernel<<<gat, 256, ATTN_SMEM>>>();
    // width pass (fuses x1 = feature + h_gate*attn_h)
    qv_kernel<<<gqv, 256, QV_SMEM>>>(feature, h_gate, wq_w, wq_b, wv_w, wv_b, 1);
    attn_kernel<<<gat, 256, ATTN_SMEM>>>();
    // final combine + 1x1 conv gate
    final_kernel<<<gqv, 256>>>(feature, predict, w_gate, conv_w, conv_b, out);
}

// round 9
// speedup vs baseline: 1.2649x; 1.2649x over previous
#include <cuda_runtime.h>
#include <cstdint>

#define NB   4
#define DIM  64
#define NSEQ 4096
#define NCLS 19

// ---------------- scratch (no allocations allowed) ----------------
__device__ float g_q    [NB * NSEQ * DIM];   // 4 MB
__device__ float g_v    [NB * NSEQ * DIM];   // 4 MB
__device__ float g_attnT[NB * DIM * NSEQ];   // 4 MB, [b][dim][n] transposed
__device__ float g_x1   [NB * NSEQ * DIM];   // 4 MB, natural [B,H,W,C]

// ---------------- helpers ----------------
static __device__ __forceinline__ float tfround(float x) {
    uint32_t r;
    asm("cvt.rna.tf32.f32 %0, %1;" : "=r"(r) : "f"(x));
    return __uint_as_float(r);
}

static __device__ __forceinline__ void mma8(float* d, const uint32_t* a, const uint32_t* b) {
    asm volatile(
        "mma.sync.aligned.m16n8k8.row.col.f32.tf32.tf32.f32 "
        "{%0,%1,%2,%3}, {%4,%5,%6,%7}, {%8,%9}, {%0,%1,%2,%3};\n"
        : "+f"(d[0]), "+f"(d[1]), "+f"(d[2]), "+f"(d[3])
        : "r"(a[0]), "r"(a[1]), "r"(a[2]), "r"(a[3]), "r"(b[0]), "r"(b[1]));
}

static __device__ __forceinline__ float sigm(float x) {
    return 1.0f / (1.0f + __expf(-x));
}

static __device__ __forceinline__ void cp16(uint32_t dst_smem, const void* src) {
    // .cg: bypass L1 — staged KV tiles are consumed from smem only
    asm volatile("cp.async.cg.shared.global [%0], [%1], 16;\n" :: "r"(dst_smem), "l"(src));
}

// ---------------- K1/K3: gather + q,v projection ----------------
#define QV_SMEM ((64 * 65 + 2 * 64 * 64) * 4)

__global__ __launch_bounds__(256) void qv_kernel(
    const float* __restrict__ feature,
    const float* __restrict__ gate,          // used only in mode 1
    const float* __restrict__ Wq, const float* __restrict__ bq,
    const float* __restrict__ Wv, const float* __restrict__ bv,
    int mode)
{
    extern __shared__ float sm[];
    float* xs  = sm;                 // 64 x 65 (padded)
    float* wqs = sm + 64 * 65;       // 64 x 64
    float* wvs = wqs + 64 * 64;      // 64 x 64

    const int b   = blockIdx.y;
    const int s   = blockIdx.x;
    const int tid = threadIdx.x;

    #pragma unroll
    for (int i = 0; i < 16; i++) {
        int lin = tid + 256 * i;
        wqs[lin] = Wq[lin];
        wvs[lin] = Wv[lin];
    }

    if (mode == 0) {
        size_t fb = (size_t)b * 262144 + (size_t)s * 64;
        #pragma unroll
        for (int i = 0; i < 16; i++) {
            int lin = tid + 256 * i;            // lin = h*64 + c
            float val = feature[fb + (size_t)(lin >> 6) * 4096 + (lin & 63)];
            xs[(lin & 63) * 65 + (lin >> 6)] = val;
        }
    } else {
        float gt = gate[0];
        size_t fb = (size_t)b * 262144 + (size_t)s * 4096;
        const float* at = g_attnT + (size_t)(b * 64 + s) * 4096;
        #pragma unroll
        for (int i = 0; i < 16; i++) {
            int lin = tid + 256 * i;            // lin = w*64 + c
            float val = feature[fb + lin] + gt * at[lin];
            g_x1[fb + lin] = val;
            xs[(lin & 63) * 65 + (lin >> 6)] = val;
        }
    }
    __syncthreads();

    const int tx = tid & 15;   // output cols tx*4..+3
    const int ty = tid >> 4;   // output rows ty*4..+3

    float accq[4][4], accv[4][4];
    #pragma unroll
    for (int i = 0; i < 4; i++)
        #pragma unroll
        for (int j = 0; j < 4; j++) { accq[i][j] = 0.f; accv[i][j] = 0.f; }

    #pragma unroll 8
    for (int k = 0; k < 64; k++) {
        float4 wq4 = *(const float4*)(wqs + k * 64 + tx * 4);
        float4 wv4 = *(const float4*)(wvs + k * 64 + tx * 4);
        #pragma unroll
        for (int i = 0; i < 4; i++) {
            float x = xs[(ty * 4 + i) * 65 + k];
            accq[i][0] += x * wq4.x; accq[i][1] += x * wq4.y;
            accq[i][2] += x * wq4.z; accq[i][3] += x * wq4.w;
            accv[i][0] += x * wv4.x; accv[i][1] += x * wv4.y;
            accv[i][2] += x * wv4.z; accv[i][3] += x * wv4.w;
        }
    }

    float4 bq4 = *(const float4*)(bq + tx * 4);
    float4 bv4 = *(const float4*)(bv + tx * 4);
    size_t ob = ((size_t)b * NSEQ + (size_t)s * 64) * 64;
    #pragma unroll
    for (int i = 0; i < 4; i++) {
        int r = ty * 4 + i;
        float4 oq, ov;
        oq.x = tfround(accq[i][0] + bq4.x);
        oq.y = tfround(accq[i][1] + bq4.y);
        oq.z = tfround(accq[i][2] + bq4.z);
        oq.w = tfround(accq[i][3] + bq4.w);
        ov.x = tfround(accv[i][0] + bv4.x);
        ov.y = tfround(accv[i][1] + bv4.y);
        ov.z = tfround(accv[i][2] + bv4.z);
        ov.w = tfround(accv[i][3] + bv4.w);
        *(float4*)(g_q + ob + (size_t)r * 64 + tx * 4) = oq;
        *(float4*)(g_v + ob + (size_t)r * 64 + tx * 4) = ov;
    }
}

// ---------------- K2/K4: fused sigmoid attention ----------------
// 512 threads / 16 warps. Warp wp: row-group rg=wp>>1 (16 rows), col-half ch=wp&1 (32 cols).
// out[n][d] = sum_m sigmoid(q[n].q[m]/8) * v[m][d]; writes g_attnT[b][d][n].
#define KV_STRIDE (64 * 68)
#define ATTN_SMEM ((4 * KV_STRIDE + 128 * 68) * 4)

__global__ __launch_bounds__(512, 1) void attn_kernel()
{
    extern __shared__ float sm[];
    float* kv  = sm;                       // [buf][K/V] 4 x (64 x 68)
    float* ssh = sm + 4 * KV_STRIDE;       // 128 x 68 (Q-stage / S / O-transpose)

    const int b   = blockIdx.y;
    const int n0  = blockIdx.x * 128;
    const int tid  = threadIdx.x;
    const int lane = tid & 31;
    const int wp   = tid >> 5;
    const int rg   = wp >> 1;      // row group 0..7
    const int ch   = wp & 1;       // column half 0..1
    const int g    = lane >> 2;
    const int t    = lane & 3;
    const int row0 = rg * 16 + g;

    const float* qb = g_q + (size_t)b * NSEQ * DIM;
    const float* vb = g_v + (size_t)b * NSEQ * DIM;

    // per-thread staging coords: 2 float4 per matrix per tile
    const int sr  = tid >> 4;          // rows sr, sr+32
    const int sc4 = (tid & 15) * 4;

    // prefetch tile 0 into buffer 0
    {
        uint32_t kdst = (uint32_t)__cvta_generic_to_shared(kv + sr * 68 + sc4);
        uint32_t vdst = kdst + (uint32_t)(KV_STRIDE * 4);
        #pragma unroll
        for (int i = 0; i < 2; i++) {
            int r = sr + 32 * i;
            cp16(kdst + i * (32 * 68 * 4), qb + (size_t)r * 64 + sc4);
            cp16(vdst + i * (32 * 68 * 4), vb + (size_t)r * 64 + sc4);
        }
        asm volatile("cp.async.commit_group;\n");
    }

    // stage Q block (128x64), preload A fragments for all 8 k-steps
    #pragma unroll
    for (int i = 0; i < 4; i++) {
        int idx = tid + 512 * i;
        int r = idx >> 4, c4 = (idx & 15) * 4;
        *(float4*)(ssh + r * 68 + c4) = *(const float4*)(qb + (size_t)(n0 + r) * 64 + c4);
    }
    __syncthreads();
    uint32_t qa[8][4];
    #pragma unroll
    for (int kk = 0; kk < 8; kk++) {
        qa[kk][0] = __float_as_uint(ssh[ row0      * 68 + kk * 8 + t]);
        qa[kk][1] = __float_as_uint(ssh[(row0 + 8) * 68 + kk * 8 + t]);
        qa[kk][2] = __float_as_uint(ssh[ row0      * 68 + kk * 8 + t + 4]);
        qa[kk][3] = __float_as_uint(ssh[(row0 + 8) * 68 + kk * 8 + t + 4]);
    }

    float oacc[4][4];
    #pragma unroll
    for (int j = 0; j < 4; j++)
        #pragma unroll
        for (int e = 0; e < 4; e++) oacc[j][e] = 0.f;

    for (int it = 0; it < 64; it++) {
        const int   cur = it & 1;
        const float* ksh = kv + (2 * cur)     * KV_STRIDE;
        const float* vsh = kv + (2 * cur + 1) * KV_STRIDE;

        // prefetch next tile into the other buffer
        if (it < 63) {
            int mn = (it + 1) * 64;
            uint32_t kdst = (uint32_t)__cvta_generic_to_shared(
                kv + (2 * (cur ^ 1)) * KV_STRIDE + sr * 68 + sc4);
            uint32_t vdst = kdst + (uint32_t)(KV_STRIDE * 4);
            #pragma unroll
            for (int i = 0; i < 2; i++) {
                int r = mn + sr + 32 * i;
                cp16(kdst + i * (32 * 68 * 4), qb + (size_t)r * 64 + sc4);
                cp16(vdst + i * (32 * 68 * 4), vb + (size_t)r * 64 + sc4);
            }
            asm volatile("cp.async.commit_group;\n");
            asm volatile("cp.async.wait_group 1;\n");
        } else {
            asm volatile("cp.async.wait_group 0;\n");
        }
        __syncthreads();   // cur buffer staged; prev-iter ssh reads done

        // GEMM1: S-slice = Q(16) @ K^T(32 cols of this half)
        float sacc[4][4];
        #pragma unroll
        for (int j = 0; j < 4; j++)
            #pragma unroll
            for (int e = 0; e < 4; e++) sacc[j][e] = 0.f;

        #pragma unroll
        for (int kk = 0; kk < 8; kk++) {
            #pragma unroll
            for (int j = 0; j < 4; j++) {
                const int c = ch * 4 + j;
                uint32_t bb[2];
                bb[0] = __float_as_uint(ksh[(c * 8 + g) * 68 + kk * 8 + t]);
                bb[1] = __float_as_uint(ksh[(c * 8 + g) * 68 + kk * 8 + t + 4]);
                mma8(sacc[j], qa[kk], bb);
            }
        }

        // sigmoid + tf32 round, deposit S slice (16 rows x 32 cols)
        #pragma unroll
        for (int j = 0; j < 4; j++) {
            const int c = ch * 4 + j;
            float s0 = sigm(sacc[j][0] * 0.125f);
            float s1 = sigm(sacc[j][1] * 0.125f);
            float s2 = sigm(sacc[j][2] * 0.125f);
            float s3 = sigm(sacc[j][3] * 0.125f);
            ssh[ row0      * 68 + c * 8 + 2 * t]     = tfround(s0);
            ssh[ row0      * 68 + c * 8 + 2 * t + 1] = tfround(s1);
            ssh[(row0 + 8) * 68 + c * 8 + 2 * t]     = tfround(s2);
            ssh[(row0 + 8) * 68 + c * 8 + 2 * t + 1] = tfround(s3);
        }
        // pair-local barrier: the 2 warps of this row-group exchange S halves
        asm volatile("bar.sync %0, 64;\n" :: "r"(rg + 1) : "memory");

        // GEMM2: O-slice(16x32) += S(16x64) @ V(64 x 32 cols of this half)
        #pragma unroll
        for (int kk = 0; kk < 8; kk++) {
            uint32_t aa[4];
            aa[0] = __float_as_uint(ssh[ row0      * 68 + kk * 8 + t]);
            aa[1] = __float_as_uint(ssh[(row0 + 8) * 68 + kk * 8 + t]);
            aa[2] = __float_as_uint(ssh[ row0      * 68 + kk * 8 + t + 4]);
            aa[3] = __float_as_uint(ssh[(row0 + 8) * 68 + kk * 8 + t + 4]);
            #pragma unroll
            for (int j = 0; j < 4; j++) {
                const int c = ch * 4 + j;
                uint32_t bb[2];
                bb[0] = __float_as_uint(vsh[(kk * 8 + t)     * 68 + c * 8 + g]);
                bb[1] = __float_as_uint(vsh[(kk * 8 + t + 4) * 68 + c * 8 + g]);
                mma8(oacc[j], aa, bb);
            }
        }
        __syncthreads();   // compute done before next prefetch reuses cur buf / S rewrite
    }

    // epilogue: smem transpose -> coalesced write of attnT[b][d][n0+r]
    #pragma unroll
    for (int j = 0; j < 4; j++) {
        const int c = ch * 4 + j;
        ssh[ row0      * 68 + c * 8 + 2 * t]     = oacc[j][0];
        ssh[ row0      * 68 + c * 8 + 2 * t + 1] = oacc[j][1];
        ssh[(row0 + 8) * 68 + c * 8 + 2 * t]     = oacc[j][2];
        ssh[(row0 + 8) * 68 + c * 8 + 2 * t + 1] = oacc[j][3];
    }
    __syncthreads();
    float* ab = g_attnT + (size_t)b * DIM * NSEQ;
    #pragma unroll
    for (int i = 0; i < 16; i++) {
        int idx = tid + 512 * i;        // 64*128 elems
        int d = idx >> 7, r = idx & 127;
        ab[(size_t)d * NSEQ + n0 + r] = ssh[r * 68 + d];
    }
}

// ---------------- K5: final gate ----------------
__global__ __launch_bounds__(256) void final_kernel(
    const float* __restrict__ feature,
    const float* __restrict__ predict,
    const float* __restrict__ wgate,
    const float* __restrict__ convw,
    const float* __restrict__ convb,
    float* __restrict__ out)
{
    __shared__ float psh[64];
    __shared__ float cw[NCLS];

    const int b = blockIdx.y;
    const int h = blockIdx.x;
    const int tid = threadIdx.x;

    if (tid < NCLS) cw[tid] = convw[tid];
    __syncthreads();

    if (tid < 64) {
        int w = tid;
        const float* pp = predict + ((size_t)(b * 64 + h) * 64 + w) * NCLS;
        float acc = convb[0];
        #pragma unroll
        for (int nc = 0; nc < NCLS; nc++) {
            float x = pp[nc];
            acc += cw[nc] / (1.0f + __expf(x));    // (1 - sigmoid(x)) = sigmoid(-x)
        }
        psh[w] = acc;
    }
    __syncthreads();

    float wg = wgate[0];
    size_t base = (size_t)(b * 64 + h) * 4096;
    #pragma unroll
    for (int i = 0; i < 16; i++) {
        int lin = tid + 256 * i;     // lin = w*64 + c
        int w = lin >> 6, c = lin & 63;
        float feat = feature[base + lin] + g_x1[base + lin]
                   + wg * g_attnT[(size_t)(b * 64 + w) * 4096 + h * 64 + c];
        out[base + lin] = psh[w] * feat;
    }
}

// ---------------- launch ----------------
extern "C" void kernel_launch(void* const* d_in, const int* in_sizes, int n_in,
                              void* d_out, int out_size)
{
    (void)in_sizes; (void)n_in; (void)out_size;
    const float* feature = (const float*)d_in[0];
    const float* predict = (const float*)d_in[1];
    const float* hq_w    = (const float*)d_in[2];
    const float* hq_b    = (const float*)d_in[3];
    const float* hv_w    = (const float*)d_in[4];
    const float* hv_b    = (const float*)d_in[5];
    const float* wq_w    = (const float*)d_in[6];
    const float* wq_b    = (const float*)d_in[7];
    const float* wv_w    = (const float*)d_in[8];
    const float* wv_b    = (const float*)d_in[9];
    const float* h_gate  = (const float*)d_in[10];
    const float* w_gate  = (const float*)d_in[11];
    const float* conv_w  = (const float*)d_in[12];
    const float* conv_b  = (const float*)d_in[13];
    float* out = (float*)d_out;

    cudaFuncSetAttribute(qv_kernel,   cudaFuncAttributeMaxDynamicSharedMemorySize, QV_SMEM);
    cudaFuncSetAttribute(attn_kernel, cudaFuncAttributeMaxDynamicSharedMemorySize, ATTN_SMEM);

    dim3 gqv(64, NB);
    dim3 gat(32, NB);

    // height pass
    qv_kernel<<<gqv, 256, QV_SMEM>>>(feature, nullptr, hq_w, hq_b, hv_w, hv_b, 0);
    attn_kernel<<<gat, 512, ATTN_SMEM>>>();
    // width pass (fuses x1 = feature + h_gate*attn_h)
    qv_kernel<<<gqv, 256, QV_SMEM>>>(feature, h_gate, wq_w, wq_b, wv_w, wv_b, 1);
    attn_kernel<<<gat, 512, ATTN_SMEM>>>();
    // final combine + 1x1 conv gate
    final_kernel<<<gqv, 256>>>(feature, predict, w_gate, conv_w, conv_b, out);
}